// round 12
// baseline (speedup 1.0000x reference)
#include <cuda_runtime.h>

// Shapes (fixed per reference setup_inputs)
#define L_DIM 4
#define B_DIM 8
#define C_DIM 256
#define HW 4096                 // 64*64 spatial
#define QROW (HW / 4)           // 1024 float4 per row
#define BC (B_DIM * C_DIM)      // 2048
#define NROWS (L_DIM * BC)      // 8192

#define CROWS 2048              // rows per 2-batch chunk
#define ATTN_BLOCKS 64          // 64 blocks x 8 warps = 512 warps = 512 (b,d) pairs

// Scratch (no allocations allowed)
__device__ float g_gap[NROWS];
__device__ float g_attn[NROWS];

__device__ __forceinline__ float sum4(float4 v) { return (v.x + v.y) + (v.z + v.w); }

// chunk-local index (0..2047) -> global row. Chunk = batches {b_base, b_base+1}.
// row = l*2048 + b*256 + c
__device__ __forceinline__ int chunk_row_from_idx(int idx, int b_base) {
    const int l   = idx >> 9;
    const int rem = idx & 511;
    const int b   = b_base + (rem >> 8);
    const int c   = rem & 255;
    return l * BC + b * C_DIM + c;
}

// ---------------------------------------------------------------------------
// One kernel, three roles selected by bid segment. All cross-role dependencies
// live across LAUNCH boundaries (graph-safe, deterministic):
//   attn(ci)  rides the launch after gap(ci)   (reads g_gap)
//   scale(ci) rides the launch after attn(ci)  (reads g_attn; input from L2)
// Heavy blocks (gap/scale) are lean 1-row copy-style blocks (~26-30 regs,
// 8 blocks/SM); scale & gap interleave 1:1 by bid parity for R/W overlap.
// ---------------------------------------------------------------------------
__global__ __launch_bounds__(256) void sffm_kernel(const float4* __restrict__ in4,
                                                   const float*  __restrict__ Wlin,
                                                   float4* __restrict__ out4,
                                                   int sc_b,    // scale chunk b_base, or -1
                                                   int at_b,    // attn  chunk b_base, or -1
                                                   int gp_b) {  // gap   chunk b_base, or -1
    const int t = threadIdx.x;
    const int n_at = (at_b >= 0) ? ATTN_BLOCKS : 0;

    if (blockIdx.x < n_at) {
        // ---------------- ATTN: warp per (b,d), coalesced W reads ----------------
        const int w    = blockIdx.x * 8 + (t >> 5);   // 0..511
        const int lane = t & 31;
        const int b    = at_b + (w >> 8);
        const int d    = w & 255;

        const float* wr = Wlin + (size_t)d * C_DIM;
        float s0 = 0.f, s1 = 0.f, s2 = 0.f, s3 = 0.f;
        #pragma unroll
        for (int k = 0; k < 8; k++) {
            const int c = lane + 32 * k;
            const float wv = __ldg(&wr[c]);           // contiguous over lanes
            s0 = fmaf(g_gap[0 * BC + b * C_DIM + c], wv, s0);
            s1 = fmaf(g_gap[1 * BC + b * C_DIM + c], wv, s1);
            s2 = fmaf(g_gap[2 * BC + b * C_DIM + c], wv, s2);
            s3 = fmaf(g_gap[3 * BC + b * C_DIM + c], wv, s3);
        }
        #pragma unroll
        for (int off = 16; off > 0; off >>= 1) {
            s0 += __shfl_xor_sync(0xffffffffu, s0, off);
            s1 += __shfl_xor_sync(0xffffffffu, s1, off);
            s2 += __shfl_xor_sync(0xffffffffu, s2, off);
            s3 += __shfl_xor_sync(0xffffffffu, s3, off);
        }
        if (lane == 0) {
            const float m = fmaxf(fmaxf(s0, s1), fmaxf(s2, s3));
            const float e0 = __expf(s0 - m);
            const float e1 = __expf(s1 - m);
            const float e2 = __expf(s2 - m);
            const float e3 = __expf(s3 - m);
            const float inv = 1.0f / (e0 + e1 + e2 + e3);
            const int base = b * C_DIM + d;
            g_attn[0 * BC + base] = e0 * inv;
            g_attn[1 * BC + base] = e1 * inv;
            g_attn[2 * BC + base] = e2 * inv;
            g_attn[3 * BC + base] = e3 * inv;
        }
        return;
    }

    // role assignment among heavy blocks
    const int b2 = blockIdx.x - n_at;
    int is_scale, j;
    if (sc_b >= 0 && gp_b >= 0) { is_scale = (b2 & 1) == 0; j = b2 >> 1; }
    else if (sc_b >= 0)         { is_scale = 1;             j = b2;      }
    else                        { is_scale = 0;             j = b2;      }

    if (is_scale) {
        // ---------------- SCALE: 1 row, pure copy-multiply ----------------
        const int row = chunk_row_from_idx(j, sc_b);
        const float a = g_attn[row];                  // written by prior launch
        const float4* p = in4 + (size_t)row * QROW;
        float4*       q = out4 + (size_t)row * QROW;

        float4 v0 = p[t];
        float4 v1 = p[t + 256];
        float4 v2 = p[t + 512];
        float4 v3 = p[t + 768];

        v0.x *= a; v0.y *= a; v0.z *= a; v0.w *= a;
        v1.x *= a; v1.y *= a; v1.z *= a; v1.w *= a;
        v2.x *= a; v2.y *= a; v2.z *= a; v2.w *= a;
        v3.x *= a; v3.y *= a; v3.z *= a; v3.w *= a;

        q[t]       = v0;
        q[t + 256] = v1;
        q[t + 512] = v2;
        q[t + 768] = v3;
    } else {
        // ---------------- GAP: 1 row -> mean ----------------
        const int row = chunk_row_from_idx(j, gp_b);
        const float4* p = in4 + (size_t)row * QROW;

        float4 v0 = p[t];
        float4 v1 = p[t + 256];
        float4 v2 = p[t + 512];
        float4 v3 = p[t + 768];

        float s = sum4(v0) + sum4(v1) + sum4(v2) + sum4(v3);
        #pragma unroll
        for (int off = 16; off > 0; off >>= 1)
            s += __shfl_xor_sync(0xffffffffu, s, off);

        __shared__ float wsum[8];
        if ((t & 31) == 0) wsum[t >> 5] = s;
        __syncthreads();
        if (t == 0) {
            float r = 0.f;
            #pragma unroll
            for (int k = 0; k < 8; k++) r += wsum[k];
            g_gap[row] = r * (1.0f / (float)HW);
        }
    }
}

// ---------------------------------------------------------------------------
extern "C" void kernel_launch(void* const* d_in, const int* in_sizes, int n_in,
                              void* d_out, int out_size) {
    const float4* in4  = (const float4*)d_in[0];
    const float*  Wlin = (const float*)d_in[1];
    float4*       out4 = (float4*)d_out;

    // Software pipeline over 2-batch chunks c0..c3 (b_base = 0,2,4,6).
    // Every dependency crosses a launch boundary:
    //   K0: gap(c0)
    //   K1: attn(c0) + gap(c1)
    //   K2: scale(c0) + attn(c1) + gap(c2)
    //   K3: scale(c1) + attn(c2) + gap(c3)
    //   K4: scale(c2) + attn(c3)
    //   K5: scale(c3)
    sffm_kernel<<<CROWS,                    256>>>(in4, Wlin, out4, -1, -1,  0);
    sffm_kernel<<<ATTN_BLOCKS + CROWS,      256>>>(in4, Wlin, out4, -1,  0,  2);
    sffm_kernel<<<ATTN_BLOCKS + 2 * CROWS,  256>>>(in4, Wlin, out4,  0,  2,  4);
    sffm_kernel<<<ATTN_BLOCKS + 2 * CROWS,  256>>>(in4, Wlin, out4,  2,  4,  6);
    sffm_kernel<<<ATTN_BLOCKS + CROWS,      256>>>(in4, Wlin, out4,  4,  6, -1);
    sffm_kernel<<<CROWS,                    256>>>(in4, Wlin, out4,  6, -1, -1);
}

// round 13
// speedup vs baseline: 1.1521x; 1.1521x over previous
#include <cuda_runtime.h>

// Shapes (fixed per reference setup_inputs)
#define L_DIM 4
#define B_DIM 8
#define C_DIM 256
#define HW 4096                 // 64*64 spatial
#define QROW (HW / 4)           // 1024 float4 per row
#define BC (B_DIM * C_DIM)      // 2048
#define NROWS (L_DIM * BC)      // 8192
#define NPAIRS BC               // (b,d) pairs = 2048

// Scratch (no allocations allowed)
__device__ float g_gap[NROWS];

__device__ __forceinline__ float sum4(float4 v) { return (v.x + v.y) + (v.z + v.w); }

// ---------------------------------------------------------------------------
// Kernel 1: GAP — 2 rows per block, 8 independent front-loaded LDG.128.
// Proven: ~23.6us @ ~5.8 TB/s (practical read ceiling). Populates L2.
// ---------------------------------------------------------------------------
__global__ __launch_bounds__(256) void gap_kernel(const float4* __restrict__ in4) {
    const int r0 = 2 * blockIdx.x;
    const int r1 = r0 + 1;
    const float4* p0 = in4 + (size_t)r0 * QROW;
    const float4* p1 = in4 + (size_t)r1 * QROW;
    const int t = threadIdx.x;

    float4 a0 = p0[t], a1 = p0[t + 256], a2 = p0[t + 512], a3 = p0[t + 768];
    float4 b0 = p1[t], b1 = p1[t + 256], b2 = p1[t + 512], b3 = p1[t + 768];

    float sA = sum4(a0) + sum4(a1) + sum4(a2) + sum4(a3);
    float sB = sum4(b0) + sum4(b1) + sum4(b2) + sum4(b3);

    #pragma unroll
    for (int off = 16; off > 0; off >>= 1) {
        sA += __shfl_xor_sync(0xffffffffu, sA, off);
        sB += __shfl_xor_sync(0xffffffffu, sB, off);
    }

    __shared__ float wsum[2][8];
    if ((t & 31) == 0) {
        wsum[0][t >> 5] = sA;
        wsum[1][t >> 5] = sB;
    }
    __syncthreads();

    if (t < 2) {
        float r = 0.f;
        #pragma unroll
        for (int k = 0; k < 8; k++) r += wsum[t][k];
        g_gap[r0 + t] = r * (1.0f / (float)HW);
    }
}

// ---------------------------------------------------------------------------
// Kernel 2: fused attn + scale, ONE BLOCK PER (b,d) PAIR = 4 rows (l=0..3).
// - slim attn prologue runs ONCE per 64KB (4x amortized vs R6):
//   coalesced W/gap loads, 20 shuffles, ONE __syncthreads, redundant
//   per-thread softmax (no t==0 serialization)
// - rows 0,1: 8 LDG.128 issued BEFORE the prologue (latency overlap)
// - rows 2,3: loaded after, latency hidden by other warps
// - reverse bid traversal (passive L2 reuse of gap-pass lines)
// - default write-back stores (proven fastest)
// ---------------------------------------------------------------------------
__global__ __launch_bounds__(256) void scale_kernel(const float4* __restrict__ in4,
                                                    const float*  __restrict__ Wlin,
                                                    float4* __restrict__ out4) {
    const int pair = (NPAIRS - 1) - blockIdx.x;   // reverse traversal
    const int b = pair >> 8;
    const int d = pair & 255;
    const int t = threadIdx.x;

    // rows for levels 0..3 of this (b,d)
    const size_t row0 = (size_t)(0 * BC + b * C_DIM + d);
    const size_t row1 = (size_t)(1 * BC + b * C_DIM + d);
    const size_t row2 = (size_t)(2 * BC + b * C_DIM + d);
    const size_t row3 = (size_t)(3 * BC + b * C_DIM + d);

    const float4* p0 = in4 + row0 * QROW;
    const float4* p1 = in4 + row1 * QROW;

    // ---- issue rows 0,1 loads first (overlap with attn prologue) ----
    float4 v0 = p0[t];
    float4 v1 = p0[t + 256];
    float4 v2 = p0[t + 512];
    float4 v3 = p0[t + 768];
    float4 w0 = p1[t];
    float4 w1 = p1[t + 256];
    float4 w2 = p1[t + 512];
    float4 w3 = p1[t + 768];

    // ---- slim attn prologue (once for all 4 rows) ----
    const float wt = __ldg(&Wlin[d * C_DIM + t]);          // coalesced over t
    float s0 = g_gap[0 * BC + b * C_DIM + t] * wt;
    float s1 = g_gap[1 * BC + b * C_DIM + t] * wt;
    float s2 = g_gap[2 * BC + b * C_DIM + t] * wt;
    float s3 = g_gap[3 * BC + b * C_DIM + t] * wt;

    #pragma unroll
    for (int off = 16; off > 0; off >>= 1) {
        s0 += __shfl_xor_sync(0xffffffffu, s0, off);
        s1 += __shfl_xor_sync(0xffffffffu, s1, off);
        s2 += __shfl_xor_sync(0xffffffffu, s2, off);
        s3 += __shfl_xor_sync(0xffffffffu, s3, off);
    }

    __shared__ float sh[4][8];
    if ((t & 31) == 0) {
        sh[0][t >> 5] = s0;
        sh[1][t >> 5] = s1;
        sh[2][t >> 5] = s2;
        sh[3][t >> 5] = s3;
    }
    __syncthreads();

    // every thread finishes reduction + softmax redundantly (no 2nd sync)
    float sc0 = 0.f, sc1 = 0.f, sc2 = 0.f, sc3 = 0.f;
    #pragma unroll
    for (int k = 0; k < 8; k++) {
        sc0 += sh[0][k];
        sc1 += sh[1][k];
        sc2 += sh[2][k];
        sc3 += sh[3][k];
    }
    const float m = fmaxf(fmaxf(sc0, sc1), fmaxf(sc2, sc3));
    const float e0 = __expf(sc0 - m);
    const float e1 = __expf(sc1 - m);
    const float e2 = __expf(sc2 - m);
    const float e3 = __expf(sc3 - m);
    const float inv = 1.0f / (e0 + e1 + e2 + e3);
    const float a0 = e0 * inv;
    const float a1 = e1 * inv;
    const float a2 = e2 * inv;
    const float a3 = e3 * inv;

    // ---- rows 0,1: multiply + store ----
    float4* q0 = out4 + row0 * QROW;
    float4* q1 = out4 + row1 * QROW;
    v0.x *= a0; v0.y *= a0; v0.z *= a0; v0.w *= a0;
    v1.x *= a0; v1.y *= a0; v1.z *= a0; v1.w *= a0;
    v2.x *= a0; v2.y *= a0; v2.z *= a0; v2.w *= a0;
    v3.x *= a0; v3.y *= a0; v3.z *= a0; v3.w *= a0;
    w0.x *= a1; w0.y *= a1; w0.z *= a1; w0.w *= a1;
    w1.x *= a1; w1.y *= a1; w1.z *= a1; w1.w *= a1;
    w2.x *= a1; w2.y *= a1; w2.z *= a1; w2.w *= a1;
    w3.x *= a1; w3.y *= a1; w3.z *= a1; w3.w *= a1;
    q0[t]       = v0;
    q0[t + 256] = v1;
    q0[t + 512] = v2;
    q0[t + 768] = v3;
    q1[t]       = w0;
    q1[t + 256] = w1;
    q1[t + 512] = w2;
    q1[t + 768] = w3;

    // ---- rows 2,3: load, multiply, store ----
    const float4* p2 = in4 + row2 * QROW;
    const float4* p3 = in4 + row3 * QROW;
    float4 x0 = p2[t];
    float4 x1 = p2[t + 256];
    float4 x2 = p2[t + 512];
    float4 x3 = p2[t + 768];
    float4 y0 = p3[t];
    float4 y1 = p3[t + 256];
    float4 y2 = p3[t + 512];
    float4 y3 = p3[t + 768];

    float4* q2 = out4 + row2 * QROW;
    float4* q3 = out4 + row3 * QROW;
    x0.x *= a2; x0.y *= a2; x0.z *= a2; x0.w *= a2;
    x1.x *= a2; x1.y *= a2; x1.z *= a2; x1.w *= a2;
    x2.x *= a2; x2.y *= a2; x2.z *= a2; x2.w *= a2;
    x3.x *= a2; x3.y *= a2; x3.z *= a2; x3.w *= a2;
    y0.x *= a3; y0.y *= a3; y0.z *= a3; y0.w *= a3;
    y1.x *= a3; y1.y *= a3; y1.z *= a3; y1.w *= a3;
    y2.x *= a3; y2.y *= a3; y2.z *= a3; y2.w *= a3;
    y3.x *= a3; y3.y *= a3; y3.z *= a3; y3.w *= a3;
    q2[t]       = x0;
    q2[t + 256] = x1;
    q2[t + 512] = x2;
    q2[t + 768] = x3;
    q3[t]       = y0;
    q3[t + 256] = y1;
    q3[t + 512] = y2;
    q3[t + 768] = y3;
}

// ---------------------------------------------------------------------------
extern "C" void kernel_launch(void* const* d_in, const int* in_sizes, int n_in,
                              void* d_out, int out_size) {
    const float4* in4  = (const float4*)d_in[0];
    const float*  Wlin = (const float*)d_in[1];
    float4*       out4 = (float4*)d_out;

    gap_kernel<<<NROWS / 2, 256>>>(in4);
    scale_kernel<<<NPAIRS, 256>>>(in4, Wlin, out4);
}